// round 1
// baseline (speedup 1.0000x reference)
#include <cuda_runtime.h>

// ---------------------------------------------------------------------------
// GCN link prediction:
//   h1 = relu(agg(x  @ W1) + b1)
//   h2 = relu(agg(h1 @ W2) + b2)
//   z  =      agg(h2 @ W3) + b3
//   out[l] = dot(z[eli0[l]], z[eli1[l]])
// agg(Y)[n] = sum_{e: dst[e]==n} Y[src[e]]   (CSR-based, rebuilt every call)
// ---------------------------------------------------------------------------

namespace {
constexpr int NN   = 20000;
constexpr int EE   = 320000;
constexpr int LL   = 100000;
constexpr int DIN  = 512;
constexpr int DHID = 512;
constexpr int DOUT = 256;
}

// Scratch (device globals; no dynamic allocation allowed)
__device__ float g_Y [NN * DHID];   // GEMM output (pre-aggregation), layers 1/2
__device__ float g_H [NN * DHID];   // aggregated hidden (h1 then h2)
__device__ float g_Y3[NN * DOUT];   // layer-3 GEMM output
__device__ float g_Z [NN * DOUT];   // final node embeddings
__device__ int   g_rowptr[NN + 1];
__device__ int   g_pos[NN];         // doubles as degree counter then cursor
__device__ int   g_srcs[EE];        // edge sources bucketed by dst

// ---------------------------------------------------------------------------
// CSR construction
// ---------------------------------------------------------------------------

__global__ void k_zero_deg() {
    int i = blockIdx.x * blockDim.x + threadIdx.x;
    if (i < NN) g_pos[i] = 0;
}

__global__ void k_hist(const int* __restrict__ dst) {
    int e = blockIdx.x * blockDim.x + threadIdx.x;
    if (e < EE) atomicAdd(&g_pos[dst[e]], 1);
}

// Single-block exclusive scan over NN degree counters (1024 threads, chunked).
__global__ void k_scan() {
    __shared__ int sh[1024];
    const int tid = threadIdx.x;
    constexpr int CH = (NN + 1023) / 1024;   // 20
    const int start = tid * CH;

    int local = 0;
    #pragma unroll
    for (int i = 0; i < CH; i++) {
        int idx = start + i;
        if (idx < NN) local += g_pos[idx];
    }
    sh[tid] = local;
    __syncthreads();

    // Hillis-Steele inclusive scan of per-thread sums
    for (int off = 1; off < 1024; off <<= 1) {
        int v = (tid >= off) ? sh[tid - off] : 0;
        __syncthreads();
        sh[tid] += v;
        __syncthreads();
    }

    int run = sh[tid] - local;   // exclusive prefix at this thread's chunk
    #pragma unroll
    for (int i = 0; i < CH; i++) {
        int idx = start + i;
        if (idx < NN) {
            int d = g_pos[idx];      // read degree BEFORE overwriting
            g_rowptr[idx] = run;
            g_pos[idx]    = run;     // cursor for the scatter pass
            run += d;
        }
    }
    if (tid == 1023) g_rowptr[NN] = sh[1023];
}

__global__ void k_scatter(const int* __restrict__ src, const int* __restrict__ dst) {
    int e = blockIdx.x * blockDim.x + threadIdx.x;
    if (e < EE) {
        int idx = atomicAdd(&g_pos[dst[e]], 1);
        g_srcs[idx] = src[e];
    }
}

// ---------------------------------------------------------------------------
// SGEMM: C[M,N] = A[M,K] @ B[K,N], fp32, 128x128x8 tiles, 8x8 per thread
// ---------------------------------------------------------------------------

template <int N, int K>
__device__ __forceinline__ void sgemm_body(const float* __restrict__ A,
                                           const float* __restrict__ B,
                                           float* __restrict__ C) {
    constexpr int M = NN;
    __shared__ float As[8][128];
    __shared__ float Bs[8][128];

    const int tid = threadIdx.x;          // 0..255
    const int bx  = blockIdx.x;           // along N
    const int by  = blockIdx.y;           // along M

    // A tile load mapping: 128 rows x 8 cols -> one float4 per thread
    const int arow = tid >> 1;            // 0..127
    const int acol = (tid & 1) << 2;      // 0 or 4
    // B tile load mapping: 8 rows x 128 cols -> one float4 per thread
    const int brow = tid >> 5;            // 0..7
    const int bcol = (tid & 31) << 2;     // 0..124

    const int grow = by * 128 + arow;
    const bool aval = (grow < M);
    const float* Ap = A + (size_t)grow * K;
    const float* Bp = B + (size_t)bx * 128;

    // Thread's 8x8 tile position inside the 128x128 block tile
    const int tx = (tid & 15) << 3;
    const int ty = (tid >> 4) << 3;

    float acc[8][8];
    #pragma unroll
    for (int i = 0; i < 8; i++)
        #pragma unroll
        for (int j = 0; j < 8; j++) acc[i][j] = 0.0f;

    for (int k0 = 0; k0 < K; k0 += 8) {
        float4 av = aval ? *(const float4*)(Ap + k0 + acol)
                         : make_float4(0.f, 0.f, 0.f, 0.f);
        As[acol + 0][arow] = av.x;
        As[acol + 1][arow] = av.y;
        As[acol + 2][arow] = av.z;
        As[acol + 3][arow] = av.w;
        *(float4*)&Bs[brow][bcol] = *(const float4*)(Bp + (size_t)(k0 + brow) * N + bcol);
        __syncthreads();

        #pragma unroll
        for (int k = 0; k < 8; k++) {
            float ar[8], br[8];
            *(float4*)&ar[0] = *(const float4*)&As[k][ty];
            *(float4*)&ar[4] = *(const float4*)&As[k][ty + 4];
            *(float4*)&br[0] = *(const float4*)&Bs[k][tx];
            *(float4*)&br[4] = *(const float4*)&Bs[k][tx + 4];
            #pragma unroll
            for (int i = 0; i < 8; i++)
                #pragma unroll
                for (int j = 0; j < 8; j++)
                    acc[i][j] += ar[i] * br[j];
        }
        __syncthreads();
    }

    #pragma unroll
    for (int i = 0; i < 8; i++) {
        int row = by * 128 + ty + i;
        if (row < M) {
            float* Cp = C + (size_t)row * N + bx * 128 + tx;
            *(float4*)(Cp + 0) = make_float4(acc[i][0], acc[i][1], acc[i][2], acc[i][3]);
            *(float4*)(Cp + 4) = make_float4(acc[i][4], acc[i][5], acc[i][6], acc[i][7]);
        }
    }
}

__global__ void __launch_bounds__(256) k_gemm_l1(const float* __restrict__ A,
                                                 const float* __restrict__ B) {
    sgemm_body<DHID, DIN>(A, B, g_Y);
}
__global__ void __launch_bounds__(256) k_gemm_l2(const float* __restrict__ B) {
    sgemm_body<DHID, DHID>(g_H, B, g_Y);
}
__global__ void __launch_bounds__(256) k_gemm_l3(const float* __restrict__ B) {
    sgemm_body<DOUT, DHID>(g_H, B, g_Y3);
}

// ---------------------------------------------------------------------------
// Aggregation: O[n] = (sum_{i in rowptr[n]..rowptr[n+1]} Y[srcs[i]]) + bias
// One block per node, D/4 threads, one float4 per thread.
// ---------------------------------------------------------------------------

template <int D, bool RELU>
__device__ __forceinline__ void agg_body(const float* __restrict__ Y,
                                         const float* __restrict__ bias,
                                         float* __restrict__ O) {
    const int n = blockIdx.x;
    const int c = threadIdx.x * 4;
    const int beg = g_rowptr[n];
    const int end = g_rowptr[n + 1];

    float4 acc = make_float4(0.f, 0.f, 0.f, 0.f);
    int i = beg;
    for (; i + 1 < end; i += 2) {
        int s0 = g_srcs[i];
        int s1 = g_srcs[i + 1];
        float4 v0 = *(const float4*)(Y + (size_t)s0 * D + c);
        float4 v1 = *(const float4*)(Y + (size_t)s1 * D + c);
        acc.x += v0.x + v1.x;
        acc.y += v0.y + v1.y;
        acc.z += v0.z + v1.z;
        acc.w += v0.w + v1.w;
    }
    if (i < end) {
        int s0 = g_srcs[i];
        float4 v0 = *(const float4*)(Y + (size_t)s0 * D + c);
        acc.x += v0.x; acc.y += v0.y; acc.z += v0.z; acc.w += v0.w;
    }

    float4 b = *(const float4*)(bias + c);
    acc.x += b.x; acc.y += b.y; acc.z += b.z; acc.w += b.w;
    if (RELU) {
        acc.x = fmaxf(acc.x, 0.f);
        acc.y = fmaxf(acc.y, 0.f);
        acc.z = fmaxf(acc.z, 0.f);
        acc.w = fmaxf(acc.w, 0.f);
    }
    *(float4*)(O + (size_t)n * D + c) = acc;
}

__global__ void k_agg_hid(const float* __restrict__ bias) {
    agg_body<DHID, true>(g_Y, bias, g_H);
}
__global__ void k_agg_out(const float* __restrict__ bias) {
    agg_body<DOUT, false>(g_Y3, bias, g_Z);
}

// ---------------------------------------------------------------------------
// Decode: out[l] = dot(z[eli[0][l]], z[eli[1][l]]), one warp per label edge
// ---------------------------------------------------------------------------

__global__ void k_decode(const int* __restrict__ eli, float* __restrict__ out) {
    int g = blockIdx.x * blockDim.x + threadIdx.x;
    int w = g >> 5;
    int lane = g & 31;
    if (w >= LL) return;

    int a = eli[w];
    int b = eli[LL + w];
    const float4* za = (const float4*)(g_Z + (size_t)a * DOUT);
    const float4* zb = (const float4*)(g_Z + (size_t)b * DOUT);

    float4 x0 = za[lane],      y0 = zb[lane];
    float4 x1 = za[lane + 32], y1 = zb[lane + 32];
    float s = x0.x * y0.x + x0.y * y0.y + x0.z * y0.z + x0.w * y0.w
            + x1.x * y1.x + x1.y * y1.y + x1.z * y1.z + x1.w * y1.w;

    #pragma unroll
    for (int o = 16; o; o >>= 1) s += __shfl_xor_sync(0xffffffffu, s, o);
    if (lane == 0) out[w] = s;
}

// ---------------------------------------------------------------------------
// Launch
// ---------------------------------------------------------------------------

extern "C" void kernel_launch(void* const* d_in, const int* in_sizes, int n_in,
                              void* d_out, int out_size) {
    (void)in_sizes; (void)n_in; (void)out_size;
    const float* x   = (const float*)d_in[0];
    const int*   ei  = (const int*)  d_in[1];   // [2, EE]: row0=src, row1=dst
    const int*   eli = (const int*)  d_in[2];   // [2, LL]
    const float* W1  = (const float*)d_in[3];
    const float* b1  = (const float*)d_in[4];
    const float* W2  = (const float*)d_in[5];
    const float* b2  = (const float*)d_in[6];
    const float* W3  = (const float*)d_in[7];
    const float* b3  = (const float*)d_in[8];
    float* out = (float*)d_out;

    const int* src = ei;
    const int* dst = ei + EE;

    // CSR build (by dst)
    k_zero_deg<<<(NN + 255) / 256, 256>>>();
    k_hist<<<(EE + 255) / 256, 256>>>(dst);
    k_scan<<<1, 1024>>>();
    k_scatter<<<(EE + 255) / 256, 256>>>(src, dst);

    const dim3 gHID(DHID / 128, (NN + 127) / 128);
    const dim3 gOUT(DOUT / 128, (NN + 127) / 128);

    // Layer 1
    k_gemm_l1<<<gHID, 256>>>(x, W1);
    k_agg_hid<<<NN, DHID / 4>>>(b1);
    // Layer 2
    k_gemm_l2<<<gHID, 256>>>(W2);
    k_agg_hid<<<NN, DHID / 4>>>(b2);
    // Layer 3 (GEMM first -> aggregate at width 256)
    k_gemm_l3<<<gOUT, 256>>>(W3);
    k_agg_out<<<NN, DOUT / 4>>>(b3);

    // Decode
    k_decode<<<(LL * 32 + 255) / 256, 256>>>(eli, out);
}

// round 3
// speedup vs baseline: 2.3461x; 2.3461x over previous
#include <cuda_runtime.h>
#include <cstdint>

// ---------------------------------------------------------------------------
// GCN link prediction:
//   h1 = relu(agg(x  @ W1) + b1)
//   h2 = relu(agg(h1 @ W2) + b2)
//   z  =      agg(h2 @ W3) + b3
//   out[l] = dot(z[eli0[l]], z[eli1[l]])
// agg(Y)[n] = sum_{e: dst[e]==n} Y[src[e]]   (CSR-based, rebuilt every call)
// GEMMs: TF32 tensor-core mma.sync (fp32 accumulate).
// ---------------------------------------------------------------------------

namespace {
constexpr int NN   = 20000;
constexpr int EE   = 320000;
constexpr int LL   = 100000;
constexpr int DIN  = 512;
constexpr int DHID = 512;
constexpr int DOUT = 256;
}

// Scratch (device globals; no dynamic allocation allowed)
__device__ float g_Y [NN * DHID];   // GEMM output (pre-aggregation), layers 1/2
__device__ float g_H [NN * DHID];   // aggregated hidden (h1 then h2)
__device__ float g_Y3[NN * DOUT];   // layer-3 GEMM output
__device__ float g_Z [NN * DOUT];   // final node embeddings
__device__ int   g_rowptr[NN + 1];
__device__ int   g_pos[NN];         // doubles as degree counter then cursor
__device__ int   g_srcs[EE];        // edge sources bucketed by dst

// ---------------------------------------------------------------------------
// CSR construction
// ---------------------------------------------------------------------------

__global__ void k_zero_deg() {
    int i = blockIdx.x * blockDim.x + threadIdx.x;
    if (i < NN) g_pos[i] = 0;
}

__global__ void k_hist(const int* __restrict__ dst) {
    int e = blockIdx.x * blockDim.x + threadIdx.x;
    if (e < EE) atomicAdd(&g_pos[dst[e]], 1);
}

__global__ void k_scan() {
    __shared__ int sh[1024];
    const int tid = threadIdx.x;
    constexpr int CH = (NN + 1023) / 1024;   // 20
    const int start = tid * CH;

    int local = 0;
    #pragma unroll
    for (int i = 0; i < CH; i++) {
        int idx = start + i;
        if (idx < NN) local += g_pos[idx];
    }
    sh[tid] = local;
    __syncthreads();

    for (int off = 1; off < 1024; off <<= 1) {
        int v = (tid >= off) ? sh[tid - off] : 0;
        __syncthreads();
        sh[tid] += v;
        __syncthreads();
    }

    int run = sh[tid] - local;
    #pragma unroll
    for (int i = 0; i < CH; i++) {
        int idx = start + i;
        if (idx < NN) {
            int d = g_pos[idx];
            g_rowptr[idx] = run;
            g_pos[idx]    = run;
            run += d;
        }
    }
    if (tid == 1023) g_rowptr[NN] = sh[1023];
}

__global__ void k_scatter(const int* __restrict__ src, const int* __restrict__ dst) {
    int e = blockIdx.x * blockDim.x + threadIdx.x;
    if (e < EE) {
        int idx = atomicAdd(&g_pos[dst[e]], 1);
        g_srcs[idx] = src[e];
    }
}

// ---------------------------------------------------------------------------
// TF32 tensor-core GEMM: C[M,N] = A[M,K] @ B[K,N]
// Block tile 128x128, BK=16, 256 threads (8 warps, each 64x32), double buffer.
// A stored k-major in smem (transposed), PAD=8 -> conflict-free frag loads.
// ---------------------------------------------------------------------------

#define BM 128
#define BN 128
#define BK 16
#define APAD 8
#define BPAD 8

__device__ __forceinline__ uint32_t f2tf32(float x) {
    uint32_t r;
    asm("cvt.rna.tf32.f32 %0, %1;" : "=r"(r) : "f"(x));
    return r;
}

__device__ __forceinline__ void mma_tf32(float* c,
                                         uint32_t a0, uint32_t a1, uint32_t a2, uint32_t a3,
                                         uint32_t b0, uint32_t b1) {
    asm volatile(
        "mma.sync.aligned.m16n8k8.row.col.f32.tf32.tf32.f32 "
        "{%0,%1,%2,%3}, {%4,%5,%6,%7}, {%8,%9}, {%0,%1,%2,%3};\n"
        : "+f"(c[0]), "+f"(c[1]), "+f"(c[2]), "+f"(c[3])
        : "r"(a0), "r"(a1), "r"(a2), "r"(a3), "r"(b0), "r"(b1));
}

template <int N, int K>
__device__ __forceinline__ void gemm_tf32_body(const float* __restrict__ A,
                                               const float* __restrict__ B,
                                               float* __restrict__ C) {
    constexpr int M = NN;
    __shared__ float As[2][BK][BM + APAD];   // k-major (transposed)
    __shared__ float Bs[2][BK][BN + BPAD];   // k rows, n cols

    const int tid  = threadIdx.x;
    const int bx   = blockIdx.x;             // along N
    const int by   = blockIdx.y;             // along M
    const int wid  = tid >> 5;
    const int lane = tid & 31;
    const int gid  = lane >> 2;              // 0..7
    const int tig  = lane & 3;               // 0..3

    const int wr = wid & 1;                  // warp row (2)
    const int wc = wid >> 1;                 // warp col (4)
    const int wm0 = wr * 64;
    const int wn0 = wc * 32;

    float acc[4][4][4];
    #pragma unroll
    for (int i = 0; i < 4; i++)
        #pragma unroll
        for (int j = 0; j < 4; j++)
            #pragma unroll
            for (int q = 0; q < 4; q++) acc[i][j][q] = 0.0f;

    float4 aReg[2], bReg[2];

    auto loadGlobal = [&](int k0) {
        #pragma unroll
        for (int l = 0; l < 2; l++) {
            int fidx = tid + l * 256;
            int ar = fidx >> 2, ac4 = fidx & 3;
            int grow = by * BM + ar;
            aReg[l] = (grow < M) ? *(const float4*)(A + (size_t)grow * K + k0 + ac4 * 4)
                                 : make_float4(0.f, 0.f, 0.f, 0.f);
            int br = fidx >> 5, bc4 = fidx & 31;
            bReg[l] = *(const float4*)(B + (size_t)(k0 + br) * N + bx * BN + bc4 * 4);
        }
    };

    auto storeSmem = [&](int buf) {
        #pragma unroll
        for (int l = 0; l < 2; l++) {
            int fidx = tid + l * 256;
            int ar = fidx >> 2, ac4 = fidx & 3;
            As[buf][ac4 * 4 + 0][ar] = __uint_as_float(f2tf32(aReg[l].x));
            As[buf][ac4 * 4 + 1][ar] = __uint_as_float(f2tf32(aReg[l].y));
            As[buf][ac4 * 4 + 2][ar] = __uint_as_float(f2tf32(aReg[l].z));
            As[buf][ac4 * 4 + 3][ar] = __uint_as_float(f2tf32(aReg[l].w));
            int br = fidx >> 5, bc4 = fidx & 31;
            float4 bv;
            bv.x = __uint_as_float(f2tf32(bReg[l].x));
            bv.y = __uint_as_float(f2tf32(bReg[l].y));
            bv.z = __uint_as_float(f2tf32(bReg[l].z));
            bv.w = __uint_as_float(f2tf32(bReg[l].w));
            *(float4*)&Bs[buf][br][bc4 * 4] = bv;
        }
    };

    // Prologue
    loadGlobal(0);
    storeSmem(0);
    __syncthreads();

    constexpr int NT = K / BK;
    int cur = 0;
    for (int kt = 0; kt < NT; kt++) {
        if (kt + 1 < NT) loadGlobal((kt + 1) * BK);

        #pragma unroll
        for (int ks = 0; ks < 2; ks++) {
            const int kb = ks * 8;
            uint32_t af[4][4], bf[4][2];
            #pragma unroll
            for (int mi = 0; mi < 4; mi++) {
                int m0 = wm0 + mi * 16;
                af[mi][0] = __float_as_uint(As[cur][kb + tig    ][m0 + gid    ]);
                af[mi][1] = __float_as_uint(As[cur][kb + tig    ][m0 + gid + 8]);
                af[mi][2] = __float_as_uint(As[cur][kb + tig + 4][m0 + gid    ]);
                af[mi][3] = __float_as_uint(As[cur][kb + tig + 4][m0 + gid + 8]);
            }
            #pragma unroll
            for (int ni = 0; ni < 4; ni++) {
                int n0 = wn0 + ni * 8;
                bf[ni][0] = __float_as_uint(Bs[cur][kb + tig    ][n0 + gid]);
                bf[ni][1] = __float_as_uint(Bs[cur][kb + tig + 4][n0 + gid]);
            }
            #pragma unroll
            for (int mi = 0; mi < 4; mi++)
                #pragma unroll
                for (int ni = 0; ni < 4; ni++)
                    mma_tf32(acc[mi][ni], af[mi][0], af[mi][1], af[mi][2], af[mi][3],
                             bf[ni][0], bf[ni][1]);
        }

        if (kt + 1 < NT) {
            storeSmem(cur ^ 1);
            __syncthreads();
            cur ^= 1;
        }
    }

    // Epilogue: c0/c1 -> (row, 2*tig), c2/c3 -> (row+8, 2*tig)
    #pragma unroll
    for (int mi = 0; mi < 4; mi++) {
        #pragma unroll
        for (int ni = 0; ni < 4; ni++) {
            int row0 = by * BM + wm0 + mi * 16 + gid;
            int col  = bx * BN + wn0 + ni * 8 + tig * 2;
            if (row0 < M)
                *(float2*)(C + (size_t)row0 * N + col) =
                    make_float2(acc[mi][ni][0], acc[mi][ni][1]);
            int row1 = row0 + 8;
            if (row1 < M)
                *(float2*)(C + (size_t)row1 * N + col) =
                    make_float2(acc[mi][ni][2], acc[mi][ni][3]);
        }
    }
}

__global__ void __launch_bounds__(256) k_gemm_l1(const float* __restrict__ A,
                                                 const float* __restrict__ B) {
    gemm_tf32_body<DHID, DIN>(A, B, g_Y);
}
__global__ void __launch_bounds__(256) k_gemm_l2(const float* __restrict__ B) {
    gemm_tf32_body<DHID, DHID>(g_H, B, g_Y);
}
__global__ void __launch_bounds__(256) k_gemm_l3(const float* __restrict__ B) {
    gemm_tf32_body<DOUT, DHID>(g_H, B, g_Y3);
}

// ---------------------------------------------------------------------------
// Aggregation: O[n] = (sum_{i in rowptr[n]..rowptr[n+1]} Y[srcs[i]]) + bias
// ---------------------------------------------------------------------------

template <int D, bool RELU>
__device__ __forceinline__ void agg_body(const float* __restrict__ Y,
                                         const float* __restrict__ bias,
                                         float* __restrict__ O) {
    const int n = blockIdx.x;
    const int c = threadIdx.x * 4;
    const int beg = g_rowptr[n];
    const int end = g_rowptr[n + 1];

    float4 acc = make_float4(0.f, 0.f, 0.f, 0.f);
    int i = beg;
    for (; i + 1 < end; i += 2) {
        int s0 = g_srcs[i];
        int s1 = g_srcs[i + 1];
        float4 v0 = *(const float4*)(Y + (size_t)s0 * D + c);
        float4 v1 = *(const float4*)(Y + (size_t)s1 * D + c);
        acc.x += v0.x + v1.x;
        acc.y += v0.y + v1.y;
        acc.z += v0.z + v1.z;
        acc.w += v0.w + v1.w;
    }
    if (i < end) {
        int s0 = g_srcs[i];
        float4 v0 = *(const float4*)(Y + (size_t)s0 * D + c);
        acc.x += v0.x; acc.y += v0.y; acc.z += v0.z; acc.w += v0.w;
    }

    float4 b = *(const float4*)(bias + c);
    acc.x += b.x; acc.y += b.y; acc.z += b.z; acc.w += b.w;
    if (RELU) {
        acc.x = fmaxf(acc.x, 0.f);
        acc.y = fmaxf(acc.y, 0.f);
        acc.z = fmaxf(acc.z, 0.f);
        acc.w = fmaxf(acc.w, 0.f);
    }
    *(float4*)(O + (size_t)n * D + c) = acc;
}

__global__ void k_agg_hid(const float* __restrict__ bias) {
    agg_body<DHID, true>(g_Y, bias, g_H);
}
__global__ void k_agg_out(const float* __restrict__ bias) {
    agg_body<DOUT, false>(g_Y3, bias, g_Z);
}

// ---------------------------------------------------------------------------
// Decode: out[l] = dot(z[eli[0][l]], z[eli[1][l]]), one warp per label edge
// ---------------------------------------------------------------------------

__global__ void k_decode(const int* __restrict__ eli, float* __restrict__ out) {
    int g = blockIdx.x * blockDim.x + threadIdx.x;
    int w = g >> 5;
    int lane = g & 31;
    if (w >= LL) return;

    int a = eli[w];
    int b = eli[LL + w];
    const float4* za = (const float4*)(g_Z + (size_t)a * DOUT);
    const float4* zb = (const float4*)(g_Z + (size_t)b * DOUT);

    float4 x0 = za[lane],      y0 = zb[lane];
    float4 x1 = za[lane + 32], y1 = zb[lane + 32];
    float s = x0.x * y0.x + x0.y * y0.y + x0.z * y0.z + x0.w * y0.w
            + x1.x * y1.x + x1.y * y1.y + x1.z * y1.z + x1.w * y1.w;

    #pragma unroll
    for (int o = 16; o; o >>= 1) s += __shfl_xor_sync(0xffffffffu, s, o);
    if (lane == 0) out[w] = s;
}

// ---------------------------------------------------------------------------
// Launch
// ---------------------------------------------------------------------------

extern "C" void kernel_launch(void* const* d_in, const int* in_sizes, int n_in,
                              void* d_out, int out_size) {
    (void)in_sizes; (void)n_in; (void)out_size;
    const float* x   = (const float*)d_in[0];
    const int*   ei  = (const int*)  d_in[1];   // [2, EE]: row0=src, row1=dst
    const int*   eli = (const int*)  d_in[2];   // [2, LL]
    const float* W1  = (const float*)d_in[3];
    const float* b1  = (const float*)d_in[4];
    const float* W2  = (const float*)d_in[5];
    const float* b2  = (const float*)d_in[6];
    const float* W3  = (const float*)d_in[7];
    const float* b3  = (const float*)d_in[8];
    float* out = (float*)d_out;

    const int* src = ei;
    const int* dst = ei + EE;

    // CSR build (by dst)
    k_zero_deg<<<(NN + 255) / 256, 256>>>();
    k_hist<<<(EE + 255) / 256, 256>>>(dst);
    k_scan<<<1, 1024>>>();
    k_scatter<<<(EE + 255) / 256, 256>>>(src, dst);

    const dim3 gHID(DHID / BN, (NN + BM - 1) / BM);
    const dim3 gOUT(DOUT / BN, (NN + BM - 1) / BM);

    // Layer 1
    k_gemm_l1<<<gHID, 256>>>(x, W1);
    k_agg_hid<<<NN, DHID / 4>>>(b1);
    // Layer 2
    k_gemm_l2<<<gHID, 256>>>(W2);
    k_agg_hid<<<NN, DHID / 4>>>(b2);
    // Layer 3 (GEMM first -> aggregate at width 256)
    k_gemm_l3<<<gOUT, 256>>>(W3);
    k_agg_out<<<NN, DOUT / 4>>>(b3);

    // Decode
    k_decode<<<(LL * 32 + 255) / 256, 256>>>(eli, out);
}

// round 4
// speedup vs baseline: 2.4500x; 1.0443x over previous
#include <cuda_runtime.h>
#include <cuda_fp16.h>
#include <cstdint>

// ---------------------------------------------------------------------------
// GCN link prediction:
//   h1 = relu(agg(x  @ W1) + b1)
//   h2 = relu(agg(h1 @ W2) + b2)
//   z  =      agg(h2 @ W3) + b3
//   out[l] = dot(z[eli0[l]], z[eli1[l]])
// agg(Y)[n] = sum_{e: dst[e]==n} Y[src[e]]   (CSR-based, rebuilt every call)
// GEMMs: TF32 tensor-core mma.sync (fp32 accumulate).
// Gather operands (GEMM outputs Y, final z) stored fp16 to halve L2 traffic;
// all accumulation in fp32.
// ---------------------------------------------------------------------------

namespace {
constexpr int NN   = 20000;
constexpr int EE   = 320000;
constexpr int LL   = 100000;
constexpr int DIN  = 512;
constexpr int DHID = 512;
constexpr int DOUT = 256;
}

// Scratch (device globals; no dynamic allocation allowed)
__device__ __half g_Yh [NN * DHID];   // GEMM output (pre-agg), layers 1/2, fp16
__device__ float  g_H  [NN * DHID];   // aggregated hidden (h1 then h2), fp32
__device__ __half g_Y3h[NN * DOUT];   // layer-3 GEMM output, fp16
__device__ __half g_Zh [NN * DOUT];   // final node embeddings, fp16
__device__ int    g_rowptr[NN + 1];
__device__ int    g_pos[NN];
__device__ int    g_srcs[EE];

// ---------------------------------------------------------------------------
// CSR construction
// ---------------------------------------------------------------------------

__global__ void k_zero_deg() {
    int i = blockIdx.x * blockDim.x + threadIdx.x;
    if (i < NN) g_pos[i] = 0;
}

__global__ void k_hist(const int* __restrict__ dst) {
    int e = blockIdx.x * blockDim.x + threadIdx.x;
    if (e < EE) atomicAdd(&g_pos[dst[e]], 1);
}

__global__ void k_scan() {
    __shared__ int sh[1024];
    const int tid = threadIdx.x;
    constexpr int CH = (NN + 1023) / 1024;   // 20
    const int start = tid * CH;

    int local = 0;
    #pragma unroll
    for (int i = 0; i < CH; i++) {
        int idx = start + i;
        if (idx < NN) local += g_pos[idx];
    }
    sh[tid] = local;
    __syncthreads();

    for (int off = 1; off < 1024; off <<= 1) {
        int v = (tid >= off) ? sh[tid - off] : 0;
        __syncthreads();
        sh[tid] += v;
        __syncthreads();
    }

    int run = sh[tid] - local;
    #pragma unroll
    for (int i = 0; i < CH; i++) {
        int idx = start + i;
        if (idx < NN) {
            int d = g_pos[idx];
            g_rowptr[idx] = run;
            g_pos[idx]    = run;
            run += d;
        }
    }
    if (tid == 1023) g_rowptr[NN] = sh[1023];
}

__global__ void k_scatter(const int* __restrict__ src, const int* __restrict__ dst) {
    int e = blockIdx.x * blockDim.x + threadIdx.x;
    if (e < EE) {
        int idx = atomicAdd(&g_pos[dst[e]], 1);
        g_srcs[idx] = src[e];
    }
}

// ---------------------------------------------------------------------------
// TF32 tensor-core GEMM: C[M,N] = A[M,K] @ B[K,N]; C stored fp16.
// Block tile 128x128, BK=16, 256 threads (8 warps, each 64x32), double buffer.
// ---------------------------------------------------------------------------

#define BM 128
#define BN 128
#define BK 16
#define APAD 8
#define BPAD 8

__device__ __forceinline__ uint32_t f2tf32(float x) {
    uint32_t r;
    asm("cvt.rna.tf32.f32 %0, %1;" : "=r"(r) : "f"(x));
    return r;
}

__device__ __forceinline__ void mma_tf32(float* c,
                                         uint32_t a0, uint32_t a1, uint32_t a2, uint32_t a3,
                                         uint32_t b0, uint32_t b1) {
    asm volatile(
        "mma.sync.aligned.m16n8k8.row.col.f32.tf32.tf32.f32 "
        "{%0,%1,%2,%3}, {%4,%5,%6,%7}, {%8,%9}, {%0,%1,%2,%3};\n"
        : "+f"(c[0]), "+f"(c[1]), "+f"(c[2]), "+f"(c[3])
        : "r"(a0), "r"(a1), "r"(a2), "r"(a3), "r"(b0), "r"(b1));
}

template <int N, int K>
__device__ __forceinline__ void gemm_tf32_body(const float* __restrict__ A,
                                               const float* __restrict__ B,
                                               __half* __restrict__ C) {
    constexpr int M = NN;
    __shared__ float As[2][BK][BM + APAD];   // k-major (transposed)
    __shared__ float Bs[2][BK][BN + BPAD];   // k rows, n cols

    const int tid  = threadIdx.x;
    const int bx   = blockIdx.x;             // along N
    const int by   = blockIdx.y;             // along M
    const int wid  = tid >> 5;
    const int lane = tid & 31;
    const int gid  = lane >> 2;              // 0..7
    const int tig  = lane & 3;               // 0..3

    const int wr = wid & 1;
    const int wc = wid >> 1;
    const int wm0 = wr * 64;
    const int wn0 = wc * 32;

    float acc[4][4][4];
    #pragma unroll
    for (int i = 0; i < 4; i++)
        #pragma unroll
        for (int j = 0; j < 4; j++)
            #pragma unroll
            for (int q = 0; q < 4; q++) acc[i][j][q] = 0.0f;

    float4 aReg[2], bReg[2];

    auto loadGlobal = [&](int k0) {
        #pragma unroll
        for (int l = 0; l < 2; l++) {
            int fidx = tid + l * 256;
            int ar = fidx >> 2, ac4 = fidx & 3;
            int grow = by * BM + ar;
            aReg[l] = (grow < M) ? *(const float4*)(A + (size_t)grow * K + k0 + ac4 * 4)
                                 : make_float4(0.f, 0.f, 0.f, 0.f);
            int br = fidx >> 5, bc4 = fidx & 31;
            bReg[l] = *(const float4*)(B + (size_t)(k0 + br) * N + bx * BN + bc4 * 4);
        }
    };

    auto storeSmem = [&](int buf) {
        #pragma unroll
        for (int l = 0; l < 2; l++) {
            int fidx = tid + l * 256;
            int ar = fidx >> 2, ac4 = fidx & 3;
            As[buf][ac4 * 4 + 0][ar] = __uint_as_float(f2tf32(aReg[l].x));
            As[buf][ac4 * 4 + 1][ar] = __uint_as_float(f2tf32(aReg[l].y));
            As[buf][ac4 * 4 + 2][ar] = __uint_as_float(f2tf32(aReg[l].z));
            As[buf][ac4 * 4 + 3][ar] = __uint_as_float(f2tf32(aReg[l].w));
            int br = fidx >> 5, bc4 = fidx & 31;
            float4 bv;
            bv.x = __uint_as_float(f2tf32(bReg[l].x));
            bv.y = __uint_as_float(f2tf32(bReg[l].y));
            bv.z = __uint_as_float(f2tf32(bReg[l].z));
            bv.w = __uint_as_float(f2tf32(bReg[l].w));
            *(float4*)&Bs[buf][br][bc4 * 4] = bv;
        }
    };

    loadGlobal(0);
    storeSmem(0);
    __syncthreads();

    constexpr int NT = K / BK;
    int cur = 0;
    for (int kt = 0; kt < NT; kt++) {
        if (kt + 1 < NT) loadGlobal((kt + 1) * BK);

        #pragma unroll
        for (int ks = 0; ks < 2; ks++) {
            const int kb = ks * 8;
            uint32_t af[4][4], bf[4][2];
            #pragma unroll
            for (int mi = 0; mi < 4; mi++) {
                int m0 = wm0 + mi * 16;
                af[mi][0] = __float_as_uint(As[cur][kb + tig    ][m0 + gid    ]);
                af[mi][1] = __float_as_uint(As[cur][kb + tig    ][m0 + gid + 8]);
                af[mi][2] = __float_as_uint(As[cur][kb + tig + 4][m0 + gid    ]);
                af[mi][3] = __float_as_uint(As[cur][kb + tig + 4][m0 + gid + 8]);
            }
            #pragma unroll
            for (int ni = 0; ni < 4; ni++) {
                int n0 = wn0 + ni * 8;
                bf[ni][0] = __float_as_uint(Bs[cur][kb + tig    ][n0 + gid]);
                bf[ni][1] = __float_as_uint(Bs[cur][kb + tig + 4][n0 + gid]);
            }
            #pragma unroll
            for (int mi = 0; mi < 4; mi++)
                #pragma unroll
                for (int ni = 0; ni < 4; ni++)
                    mma_tf32(acc[mi][ni], af[mi][0], af[mi][1], af[mi][2], af[mi][3],
                             bf[ni][0], bf[ni][1]);
        }

        if (kt + 1 < NT) {
            storeSmem(cur ^ 1);
            __syncthreads();
            cur ^= 1;
        }
    }

    // Epilogue -> fp16 (half2 stores: cols tig*2, tig*2+1)
    #pragma unroll
    for (int mi = 0; mi < 4; mi++) {
        #pragma unroll
        for (int ni = 0; ni < 4; ni++) {
            int row0 = by * BM + wm0 + mi * 16 + gid;
            int col  = bx * BN + wn0 + ni * 8 + tig * 2;
            if (row0 < M)
                *(__half2*)(C + (size_t)row0 * N + col) =
                    __floats2half2_rn(acc[mi][ni][0], acc[mi][ni][1]);
            int row1 = row0 + 8;
            if (row1 < M)
                *(__half2*)(C + (size_t)row1 * N + col) =
                    __floats2half2_rn(acc[mi][ni][2], acc[mi][ni][3]);
        }
    }
}

__global__ void __launch_bounds__(256) k_gemm_l1(const float* __restrict__ A,
                                                 const float* __restrict__ B) {
    gemm_tf32_body<DHID, DIN>(A, B, g_Yh);
}
__global__ void __launch_bounds__(256) k_gemm_l2(const float* __restrict__ B) {
    gemm_tf32_body<DHID, DHID>(g_H, B, g_Yh);
}
__global__ void __launch_bounds__(256) k_gemm_l3(const float* __restrict__ B) {
    gemm_tf32_body<DOUT, DHID>(g_H, B, g_Y3h);
}

// ---------------------------------------------------------------------------
// Aggregation (fp16 gather, fp32 accumulate)
// ---------------------------------------------------------------------------

__device__ __forceinline__ void acc8(float* a, uint4 v) {
    float2 f;
    f = __half22float2(*(__half2*)&v.x); a[0] += f.x; a[1] += f.y;
    f = __half22float2(*(__half2*)&v.y); a[2] += f.x; a[3] += f.y;
    f = __half22float2(*(__half2*)&v.z); a[4] += f.x; a[5] += f.y;
    f = __half22float2(*(__half2*)&v.w); a[6] += f.x; a[7] += f.y;
}

// D=512 hidden agg: 2 nodes per 128-thread block, 64 threads/node, 8 halves/thread.
__global__ void __launch_bounds__(128) k_agg_hid(const float* __restrict__ bias) {
    const int n    = blockIdx.x * 2 + (threadIdx.x >> 6);
    const int lane = threadIdx.x & 63;
    const int c    = lane * 8;
    const int beg  = g_rowptr[n];
    const int end  = g_rowptr[n + 1];

    float acc[8];
    #pragma unroll
    for (int q = 0; q < 8; q++) acc[q] = 0.0f;

    const uint4* Y = (const uint4*)(g_Yh);   // row stride = 512 halves = 64 uint4
    int i = beg;
    for (; i + 3 < end; i += 4) {
        int s0 = g_srcs[i], s1 = g_srcs[i + 1], s2 = g_srcs[i + 2], s3 = g_srcs[i + 3];
        uint4 v0 = Y[(size_t)s0 * 64 + lane];
        uint4 v1 = Y[(size_t)s1 * 64 + lane];
        uint4 v2 = Y[(size_t)s2 * 64 + lane];
        uint4 v3 = Y[(size_t)s3 * 64 + lane];
        acc8(acc, v0); acc8(acc, v1); acc8(acc, v2); acc8(acc, v3);
    }
    for (; i < end; i++) {
        uint4 v = Y[(size_t)g_srcs[i] * 64 + lane];
        acc8(acc, v);
    }

    #pragma unroll
    for (int q = 0; q < 8; q++) {
        float r = acc[q] + bias[c + q];
        acc[q] = fmaxf(r, 0.0f);
    }
    float* O = g_H + (size_t)n * DHID + c;
    *(float4*)(O + 0) = make_float4(acc[0], acc[1], acc[2], acc[3]);
    *(float4*)(O + 4) = make_float4(acc[4], acc[5], acc[6], acc[7]);
}

// D=256 output agg: 4 nodes per 128-thread block, 32 threads/node; output fp16.
__global__ void __launch_bounds__(128) k_agg_out(const float* __restrict__ bias) {
    const int n    = blockIdx.x * 4 + (threadIdx.x >> 5);
    const int lane = threadIdx.x & 31;
    const int c    = lane * 8;
    const int beg  = g_rowptr[n];
    const int end  = g_rowptr[n + 1];

    float acc[8];
    #pragma unroll
    for (int q = 0; q < 8; q++) acc[q] = 0.0f;

    const uint4* Y = (const uint4*)(g_Y3h);  // row stride = 256 halves = 32 uint4
    int i = beg;
    for (; i + 3 < end; i += 4) {
        int s0 = g_srcs[i], s1 = g_srcs[i + 1], s2 = g_srcs[i + 2], s3 = g_srcs[i + 3];
        uint4 v0 = Y[(size_t)s0 * 32 + lane];
        uint4 v1 = Y[(size_t)s1 * 32 + lane];
        uint4 v2 = Y[(size_t)s2 * 32 + lane];
        uint4 v3 = Y[(size_t)s3 * 32 + lane];
        acc8(acc, v0); acc8(acc, v1); acc8(acc, v2); acc8(acc, v3);
    }
    for (; i < end; i++) {
        uint4 v = Y[(size_t)g_srcs[i] * 32 + lane];
        acc8(acc, v);
    }

    uint4 o;
    __half2* oh = (__half2*)&o;
    #pragma unroll
    for (int q = 0; q < 4; q++)
        oh[q] = __floats2half2_rn(acc[2 * q] + bias[c + 2 * q],
                                  acc[2 * q + 1] + bias[c + 2 * q + 1]);
    *((uint4*)(g_Zh + (size_t)n * DOUT + c)) = o;
}

// ---------------------------------------------------------------------------
// Decode: out[l] = dot(z[a], z[b]); one warp/edge, 1 uint4 (8 halves) per lane.
// ---------------------------------------------------------------------------

__global__ void k_decode(const int* __restrict__ eli, float* __restrict__ out) {
    int g = blockIdx.x * blockDim.x + threadIdx.x;
    int w = g >> 5;
    int lane = g & 31;
    if (w >= LL) return;

    int a = eli[w];
    int b = eli[LL + w];
    uint4 va = ((const uint4*)(g_Zh + (size_t)a * DOUT))[lane];
    uint4 vb = ((const uint4*)(g_Zh + (size_t)b * DOUT))[lane];

    float s = 0.0f;
    const __half2* ha = (const __half2*)&va;
    const __half2* hb = (const __half2*)&vb;
    #pragma unroll
    for (int q = 0; q < 4; q++) {
        float2 fa = __half22float2(ha[q]);
        float2 fb = __half22float2(hb[q]);
        s += fa.x * fb.x + fa.y * fb.y;
    }

    #pragma unroll
    for (int o = 16; o; o >>= 1) s += __shfl_xor_sync(0xffffffffu, s, o);
    if (lane == 0) out[w] = s;
}

// ---------------------------------------------------------------------------
// Launch
// ---------------------------------------------------------------------------

extern "C" void kernel_launch(void* const* d_in, const int* in_sizes, int n_in,
                              void* d_out, int out_size) {
    (void)in_sizes; (void)n_in; (void)out_size;
    const float* x   = (const float*)d_in[0];
    const int*   ei  = (const int*)  d_in[1];   // [2, EE]: row0=src, row1=dst
    const int*   eli = (const int*)  d_in[2];   // [2, LL]
    const float* W1  = (const float*)d_in[3];
    const float* b1  = (const float*)d_in[4];
    const float* W2  = (const float*)d_in[5];
    const float* b2  = (const float*)d_in[6];
    const float* W3  = (const float*)d_in[7];
    const float* b3  = (const float*)d_in[8];
    float* out = (float*)d_out;

    const int* src = ei;
    const int* dst = ei + EE;

    // CSR build (by dst)
    k_zero_deg<<<(NN + 255) / 256, 256>>>();
    k_hist<<<(EE + 255) / 256, 256>>>(dst);
    k_scan<<<1, 1024>>>();
    k_scatter<<<(EE + 255) / 256, 256>>>(src, dst);

    const dim3 gHID(DHID / BN, (NN + BM - 1) / BM);
    const dim3 gOUT(DOUT / BN, (NN + BM - 1) / BM);

    // Layer 1
    k_gemm_l1<<<gHID, 256>>>(x, W1);
    k_agg_hid<<<NN / 2, 128>>>(b1);
    // Layer 2
    k_gemm_l2<<<gHID, 256>>>(W2);
    k_agg_hid<<<NN / 2, 128>>>(b2);
    // Layer 3 (GEMM first -> aggregate at width 256)
    k_gemm_l3<<<gOUT, 256>>>(W3);
    k_agg_out<<<NN / 4, 128>>>(b3);

    // Decode
    k_decode<<<(LL * 32 + 255) / 256, 256>>>(eli, out);
}

// round 5
// speedup vs baseline: 3.8673x; 1.5785x over previous
#include <cuda_runtime.h>
#include <cuda_fp16.h>
#include <cstdint>

// ---------------------------------------------------------------------------
// GCN link prediction:
//   h1 = relu(agg(x  @ W1) + b1)
//   h2 = relu(agg(h1 @ W2) + b2)
//   z  =      agg(h2 @ W3) + b3
//   out[l] = dot(z[eli0[l]], z[eli1[l]])
// agg(Y)[n] = sum_{e: dst[e]==n} Y[src[e]]   (CSR-based, rebuilt every call)
// GEMMs: fp16 tensor-core mma.sync m16n8k16 (fp32 accumulate, ldmatrix).
// fp16 mantissa == TF32 mantissa (10 bits): same precision as before, 2x rate.
// ---------------------------------------------------------------------------

namespace {
constexpr int NN   = 20000;
constexpr int EE   = 320000;
constexpr int LL   = 100000;
constexpr int DIN  = 512;
constexpr int DHID = 512;
constexpr int DOUT = 256;
}

// Scratch (device globals; no dynamic allocation allowed)
__device__ __half g_Yh [NN * DHID];   // GEMM output (pre-agg), layers 1/2
__device__ __half g_Hh [NN * DHID];   // aggregated hidden (h1 then h2), fp16
__device__ __half g_Y3h[NN * DOUT];   // layer-3 GEMM output
__device__ __half g_Zh [NN * DOUT];   // final node embeddings
__device__ __half g_W1h[DIN * DHID];
__device__ __half g_W2h[DHID * DHID];
__device__ __half g_W3h[DHID * DOUT];
__device__ int    g_rowptr[NN + 1];
__device__ int    g_pos[NN];
__device__ int    g_srcs[EE];

// ---------------------------------------------------------------------------
// Weight conversion fp32 -> fp16 (once per call; ~3us)
// ---------------------------------------------------------------------------

__global__ void k_cvt_w(const float* __restrict__ W1, const float* __restrict__ W2,
                        const float* __restrict__ W3) {
    int i = blockIdx.x * blockDim.x + threadIdx.x;   // float4 index
    const float* src; __half* dst; int off;
    if (i < 65536)       { src = W1; dst = g_W1h; off = i; }
    else if (i < 131072) { src = W2; dst = g_W2h; off = i - 65536; }
    else if (i < 163840) { src = W3; dst = g_W3h; off = i - 131072; }
    else return;
    float4 v = ((const float4*)src)[off];
    uint2 u;
    *(__half2*)&u.x = __floats2half2_rn(v.x, v.y);
    *(__half2*)&u.y = __floats2half2_rn(v.z, v.w);
    ((uint2*)dst)[off] = u;
}

// ---------------------------------------------------------------------------
// CSR construction
// ---------------------------------------------------------------------------

__global__ void k_zero_deg() {
    int i = blockIdx.x * blockDim.x + threadIdx.x;
    if (i < NN) g_pos[i] = 0;
}

__global__ void k_hist(const int* __restrict__ dst) {
    int e = blockIdx.x * blockDim.x + threadIdx.x;
    if (e < EE) atomicAdd(&g_pos[dst[e]], 1);
}

__global__ void k_scan() {
    __shared__ int sh[1024];
    const int tid = threadIdx.x;
    constexpr int CH = (NN + 1023) / 1024;   // 20
    const int start = tid * CH;

    int local = 0;
    #pragma unroll
    for (int i = 0; i < CH; i++) {
        int idx = start + i;
        if (idx < NN) local += g_pos[idx];
    }
    sh[tid] = local;
    __syncthreads();

    for (int off = 1; off < 1024; off <<= 1) {
        int v = (tid >= off) ? sh[tid - off] : 0;
        __syncthreads();
        sh[tid] += v;
        __syncthreads();
    }

    int run = sh[tid] - local;
    #pragma unroll
    for (int i = 0; i < CH; i++) {
        int idx = start + i;
        if (idx < NN) {
            int d = g_pos[idx];
            g_rowptr[idx] = run;
            g_pos[idx]    = run;
            run += d;
        }
    }
    if (tid == 1023) g_rowptr[NN] = sh[1023];
}

__global__ void k_scatter(const int* __restrict__ src, const int* __restrict__ dst) {
    int e = blockIdx.x * blockDim.x + threadIdx.x;
    if (e < EE) {
        int idx = atomicAdd(&g_pos[dst[e]], 1);
        g_srcs[idx] = src[e];
    }
}

// ---------------------------------------------------------------------------
// fp16 tensor-core GEMM: C[M,N] = A[M,K] @ B[K,N]; C fp16, accum fp32.
// 128x128x32 tiles, 256 threads, 8 warps (2x4, warp tile 64x32), double buffer.
// A smem [BM][BK+8] (80B rows: 16B-aligned, conflict-free for ldmatrix)
// B smem [BK][BN+8] (272B rows: 16B-aligned, conflict-free for ldmatrix.trans)
// ---------------------------------------------------------------------------

#define BM 128
#define BN 128
#define BK 32

__device__ __forceinline__ uint32_t smem_u32(const void* p) {
    return (uint32_t)__cvta_generic_to_shared(p);
}

__device__ __forceinline__ void ldm_x4(uint32_t* r, uint32_t addr) {
    asm volatile("ldmatrix.sync.aligned.m8n8.x4.shared.b16 {%0,%1,%2,%3}, [%4];"
                 : "=r"(r[0]), "=r"(r[1]), "=r"(r[2]), "=r"(r[3]) : "r"(addr));
}

__device__ __forceinline__ void ldm_x4_t(uint32_t* r, uint32_t addr) {
    asm volatile("ldmatrix.sync.aligned.m8n8.x4.trans.shared.b16 {%0,%1,%2,%3}, [%4];"
                 : "=r"(r[0]), "=r"(r[1]), "=r"(r[2]), "=r"(r[3]) : "r"(addr));
}

__device__ __forceinline__ void mma_f16(float* c, const uint32_t* a, const uint32_t* b) {
    asm volatile(
        "mma.sync.aligned.m16n8k16.row.col.f32.f16.f16.f32 "
        "{%0,%1,%2,%3}, {%4,%5,%6,%7}, {%8,%9}, {%0,%1,%2,%3};\n"
        : "+f"(c[0]), "+f"(c[1]), "+f"(c[2]), "+f"(c[3])
        : "r"(a[0]), "r"(a[1]), "r"(a[2]), "r"(a[3]), "r"(b[0]), "r"(b[1]));
}

template <int N, int K, bool AHALF>
__device__ __forceinline__ void gemm_f16_body(const void* __restrict__ Aptr,
                                              const __half* __restrict__ Bw,
                                              __half* __restrict__ C) {
    constexpr int M  = NN;
    constexpr int AS = BK + 8;    // 40 halves = 80B row
    constexpr int BS = BN + 8;    // 136 halves = 272B row
    __shared__ __half As[2][BM][AS];
    __shared__ __half Bs[2][BK][BS];

    const int tid  = threadIdx.x;
    const int bx   = blockIdx.x;
    const int by   = blockIdx.y;
    const int wid  = tid >> 5;
    const int lane = tid & 31;
    const int gid  = lane >> 2;
    const int tig  = lane & 3;

    const int wm0 = (wid & 1) * 64;
    const int wn0 = (wid >> 1) * 32;

    float acc[4][4][4];
    #pragma unroll
    for (int i = 0; i < 4; i++)
        #pragma unroll
        for (int j = 0; j < 4; j++)
            #pragma unroll
            for (int q = 0; q < 4; q++) acc[i][j][q] = 0.0f;

    uint4  aH[2];
    float4 aF[4];
    uint4  bH[2];

    auto loadGlobal = [&](int k0) {
        if (AHALF) {
            const __half* Ah = (const __half*)Aptr;
            #pragma unroll
            for (int l = 0; l < 2; l++) {
                int fidx = tid + l * 256;
                int row = fidx >> 2, col8 = fidx & 3;
                int grow = by * BM + row;
                aH[l] = (grow < M)
                    ? *(const uint4*)(Ah + (size_t)grow * K + k0 + col8 * 8)
                    : make_uint4(0u, 0u, 0u, 0u);
            }
        } else {
            const float* Af = (const float*)Aptr;
            #pragma unroll
            for (int l = 0; l < 4; l++) {
                int fidx = tid + l * 256;
                int row = fidx >> 3, col4 = fidx & 7;
                int grow = by * BM + row;
                aF[l] = (grow < M)
                    ? *(const float4*)(Af + (size_t)grow * K + k0 + col4 * 4)
                    : make_float4(0.f, 0.f, 0.f, 0.f);
            }
        }
        #pragma unroll
        for (int l = 0; l < 2; l++) {
            int fidx = tid + l * 256;
            int row = fidx >> 4, col8 = fidx & 15;
            bH[l] = *(const uint4*)(Bw + (size_t)(k0 + row) * N + bx * BN + col8 * 8);
        }
    };

    auto storeSmem = [&](int buf) {
        if (AHALF) {
            #pragma unroll
            for (int l = 0; l < 2; l++) {
                int fidx = tid + l * 256;
                int row = fidx >> 2, col8 = fidx & 3;
                *(uint4*)&As[buf][row][col8 * 8] = aH[l];
            }
        } else {
            #pragma unroll
            for (int l = 0; l < 4; l++) {
                int fidx = tid + l * 256;
                int row = fidx >> 3, col4 = fidx & 7;
                uint2 u;
                *(__half2*)&u.x = __floats2half2_rn(aF[l].x, aF[l].y);
                *(__half2*)&u.y = __floats2half2_rn(aF[l].z, aF[l].w);
                *(uint2*)&As[buf][row][col4 * 4] = u;
            }
        }
        #pragma unroll
        for (int l = 0; l < 2; l++) {
            int fidx = tid + l * 256;
            int row = fidx >> 4, col8 = fidx & 15;
            *(uint4*)&Bs[buf][row][col8 * 8] = bH[l];
        }
    };

    loadGlobal(0);
    storeSmem(0);
    __syncthreads();

    constexpr int NT = K / BK;
    int cur = 0;
    for (int kt = 0; kt < NT; kt++) {
        if (kt + 1 < NT) loadGlobal((kt + 1) * BK);

        #pragma unroll
        for (int ks = 0; ks < 2; ks++) {
            const int kb = ks * 16;
            uint32_t af[4][4], bf[4][2];
            #pragma unroll
            for (int mi = 0; mi < 4; mi++) {
                int row = wm0 + mi * 16 + (lane & 15);
                int col = kb + ((lane >> 4) << 3);
                ldm_x4(af[mi], smem_u32(&As[cur][row][col]));
            }
            #pragma unroll
            for (int nh = 0; nh < 2; nh++) {
                int row = kb + (lane & 15);
                int col = wn0 + nh * 16 + ((lane >> 4) << 3);
                uint32_t r[4];
                ldm_x4_t(r, smem_u32(&Bs[cur][row][col]));
                bf[nh * 2][0] = r[0]; bf[nh * 2][1] = r[1];
                bf[nh * 2 + 1][0] = r[2]; bf[nh * 2 + 1][1] = r[3];
            }
            #pragma unroll
            for (int mi = 0; mi < 4; mi++)
                #pragma unroll
                for (int ni = 0; ni < 4; ni++)
                    mma_f16(acc[mi][ni], af[mi], bf[ni]);
        }

        if (kt + 1 < NT) {
            storeSmem(cur ^ 1);
            __syncthreads();
            cur ^= 1;
        }
    }

    // Epilogue -> fp16
    #pragma unroll
    for (int mi = 0; mi < 4; mi++) {
        #pragma unroll
        for (int ni = 0; ni < 4; ni++) {
            int row0 = by * BM + wm0 + mi * 16 + gid;
            int col  = bx * BN + wn0 + ni * 8 + tig * 2;
            if (row0 < M)
                *(__half2*)(C + (size_t)row0 * N + col) =
                    __floats2half2_rn(acc[mi][ni][0], acc[mi][ni][1]);
            int row1 = row0 + 8;
            if (row1 < M)
                *(__half2*)(C + (size_t)row1 * N + col) =
                    __floats2half2_rn(acc[mi][ni][2], acc[mi][ni][3]);
        }
    }
}

__global__ void __launch_bounds__(256) k_gemm_l1(const float* __restrict__ A) {
    gemm_f16_body<DHID, DIN, false>(A, g_W1h, g_Yh);
}
__global__ void __launch_bounds__(256) k_gemm_l2() {
    gemm_f16_body<DHID, DHID, true>(g_Hh, g_W2h, g_Yh);
}
__global__ void __launch_bounds__(256) k_gemm_l3() {
    gemm_f16_body<DOUT, DHID, true>(g_Hh, g_W3h, g_Y3h);
}

// ---------------------------------------------------------------------------
// Aggregation (fp16 gather, fp32 accumulate, fp16 output)
// ---------------------------------------------------------------------------

__device__ __forceinline__ void acc8(float* a, uint4 v) {
    float2 f;
    f = __half22float2(*(__half2*)&v.x); a[0] += f.x; a[1] += f.y;
    f = __half22float2(*(__half2*)&v.y); a[2] += f.x; a[3] += f.y;
    f = __half22float2(*(__half2*)&v.z); a[4] += f.x; a[5] += f.y;
    f = __half22float2(*(__half2*)&v.w); a[6] += f.x; a[7] += f.y;
}

// D=512 hidden agg: 2 nodes per 128-thread block, 64 threads/node.
__global__ void __launch_bounds__(128) k_agg_hid(const float* __restrict__ bias) {
    const int n    = blockIdx.x * 2 + (threadIdx.x >> 6);
    const int lane = threadIdx.x & 63;
    const int c    = lane * 8;
    const int beg  = g_rowptr[n];
    const int end  = g_rowptr[n + 1];

    float acc[8];
    #pragma unroll
    for (int q = 0; q < 8; q++) acc[q] = 0.0f;

    const uint4* Y = (const uint4*)(g_Yh);   // row stride 64 uint4
    int i = beg;
    for (; i + 3 < end; i += 4) {
        int s0 = g_srcs[i], s1 = g_srcs[i + 1], s2 = g_srcs[i + 2], s3 = g_srcs[i + 3];
        uint4 v0 = Y[(size_t)s0 * 64 + lane];
        uint4 v1 = Y[(size_t)s1 * 64 + lane];
        uint4 v2 = Y[(size_t)s2 * 64 + lane];
        uint4 v3 = Y[(size_t)s3 * 64 + lane];
        acc8(acc, v0); acc8(acc, v1); acc8(acc, v2); acc8(acc, v3);
    }
    for (; i < end; i++) {
        uint4 v = Y[(size_t)g_srcs[i] * 64 + lane];
        acc8(acc, v);
    }

    uint4 o;
    __half2* oh = (__half2*)&o;
    #pragma unroll
    for (int q = 0; q < 4; q++) {
        float r0 = fmaxf(acc[2 * q]     + bias[c + 2 * q],     0.0f);
        float r1 = fmaxf(acc[2 * q + 1] + bias[c + 2 * q + 1], 0.0f);
        oh[q] = __floats2half2_rn(r0, r1);
    }
    *((uint4*)(g_Hh + (size_t)n * DHID + c)) = o;
}

// D=256 output agg: 4 nodes per 128-thread block, 32 threads/node.
__global__ void __launch_bounds__(128) k_agg_out(const float* __restrict__ bias) {
    const int n    = blockIdx.x * 4 + (threadIdx.x >> 5);
    const int lane = threadIdx.x & 31;
    const int c    = lane * 8;
    const int beg  = g_rowptr[n];
    const int end  = g_rowptr[n + 1];

    float acc[8];
    #pragma unroll
    for (int q = 0; q < 8; q++) acc[q] = 0.0f;

    const uint4* Y = (const uint4*)(g_Y3h);  // row stride 32 uint4
    int i = beg;
    for (; i + 3 < end; i += 4) {
        int s0 = g_srcs[i], s1 = g_srcs[i + 1], s2 = g_srcs[i + 2], s3 = g_srcs[i + 3];
        uint4 v0 = Y[(size_t)s0 * 32 + lane];
        uint4 v1 = Y[(size_t)s1 * 32 + lane];
        uint4 v2 = Y[(size_t)s2 * 32 + lane];
        uint4 v3 = Y[(size_t)s3 * 32 + lane];
        acc8(acc, v0); acc8(acc, v1); acc8(acc, v2); acc8(acc, v3);
    }
    for (; i < end; i++) {
        uint4 v = Y[(size_t)g_srcs[i] * 32 + lane];
        acc8(acc, v);
    }

    uint4 o;
    __half2* oh = (__half2*)&o;
    #pragma unroll
    for (int q = 0; q < 4; q++)
        oh[q] = __floats2half2_rn(acc[2 * q] + bias[c + 2 * q],
                                  acc[2 * q + 1] + bias[c + 2 * q + 1]);
    *((uint4*)(g_Zh + (size_t)n * DOUT + c)) = o;
}

// ---------------------------------------------------------------------------
// Decode: out[l] = dot(z[a], z[b]); one warp/edge, 8 halves per lane.
// ---------------------------------------------------------------------------

__global__ void k_decode(const int* __restrict__ eli, float* __restrict__ out) {
    int g = blockIdx.x * blockDim.x + threadIdx.x;
    int w = g >> 5;
    int lane = g & 31;
    if (w >= LL) return;

    int a = eli[w];
    int b = eli[LL + w];
    uint4 va = ((const uint4*)(g_Zh + (size_t)a * DOUT))[lane];
    uint4 vb = ((const uint4*)(g_Zh + (size_t)b * DOUT))[lane];

    float s = 0.0f;
    const __half2* ha = (const __half2*)&va;
    const __half2* hb = (const __half2*)&vb;
    #pragma unroll
    for (int q = 0; q < 4; q++) {
        float2 fa = __half22float2(ha[q]);
        float2 fb = __half22float2(hb[q]);
        s += fa.x * fb.x + fa.y * fb.y;
    }

    #pragma unroll
    for (int o = 16; o; o >>= 1) s += __shfl_xor_sync(0xffffffffu, s, o);
    if (lane == 0) out[w] = s;
}

// ---------------------------------------------------------------------------
// Launch
// ---------------------------------------------------------------------------

extern "C" void kernel_launch(void* const* d_in, const int* in_sizes, int n_in,
                              void* d_out, int out_size) {
    (void)in_sizes; (void)n_in; (void)out_size;
    const float* x   = (const float*)d_in[0];
    const int*   ei  = (const int*)  d_in[1];   // [2, EE]: row0=src, row1=dst
    const int*   eli = (const int*)  d_in[2];   // [2, LL]
    const float* W1  = (const float*)d_in[3];
    const float* b1  = (const float*)d_in[4];
    const float* W2  = (const float*)d_in[5];
    const float* b2  = (const float*)d_in[6];
    const float* W3  = (const float*)d_in[7];
    const float* b3  = (const float*)d_in[8];
    float* out = (float*)d_out;

    const int* src = ei;
    const int* dst = ei + EE;

    // Weight conversion + CSR build
    k_cvt_w<<<640, 256>>>(W1, W2, W3);
    k_zero_deg<<<(NN + 255) / 256, 256>>>();
    k_hist<<<(EE + 255) / 256, 256>>>(dst);
    k_scan<<<1, 1024>>>();
    k_scatter<<<(EE + 255) / 256, 256>>>(src, dst);

    const dim3 gHID(DHID / BN, (NN + BM - 1) / BM);
    const dim3 gOUT(DOUT / BN, (NN + BM - 1) / BM);

    // Layer 1
    k_gemm_l1<<<gHID, 256>>>(x);
    k_agg_hid<<<NN / 2, 128>>>(b1);
    // Layer 2
    k_gemm_l2<<<gHID, 256>>>();
    k_agg_hid<<<NN / 2, 128>>>(b2);
    // Layer 3 (GEMM first -> aggregate at width 256)
    k_gemm_l3<<<gOUT, 256>>>();
    k_agg_out<<<NN / 4, 128>>>(b3);

    // Decode
    k_decode<<<(LL * 32 + 255) / 256, 256>>>(eli, out);
}

// round 6
// speedup vs baseline: 4.3501x; 1.1248x over previous
#include <cuda_runtime.h>
#include <cuda_fp16.h>
#include <cstdint>

// ---------------------------------------------------------------------------
// GCN link prediction:
//   h1 = relu(agg(x  @ W1) + b1)
//   h2 = relu(agg(h1 @ W2) + b2)
//   z  =      agg(h2 @ W3) + b3
//   out[l] = dot(z[eli0[l]], z[eli1[l]])
// agg(Y)[n] = sum_{e: dst[e]==n} Y[src[e]]   (CSR-based, rebuilt every call)
// GEMMs: fp16 tensor-core mma.sync m16n8k16 (fp32 accumulate, ldmatrix).
// CSR build overlapped with {W-convert, layer-1 GEMM} on a second stream.
// ---------------------------------------------------------------------------

namespace {
constexpr int NN   = 20000;
constexpr int EE   = 320000;
constexpr int LL   = 100000;
constexpr int DIN  = 512;
constexpr int DHID = 512;
constexpr int DOUT = 256;
}

// Scratch (device globals; no dynamic allocation allowed)
__device__ __half g_Yh [NN * DHID];
__device__ __half g_Hh [NN * DHID];
__device__ __half g_Y3h[NN * DOUT];
__device__ __half g_Zh [NN * DOUT];
__device__ __half g_W1h[DIN * DHID];
__device__ __half g_W2h[DHID * DHID];
__device__ __half g_W3h[DHID * DOUT];
__device__ __align__(16) int g_rowptr[NN + 4];
__device__ __align__(16) int g_pos[NN];
__device__ int g_srcs[EE];

// ---------------------------------------------------------------------------
// Weight conversion fp32 -> fp16
// ---------------------------------------------------------------------------

__global__ void k_cvt_w(const float* __restrict__ W1, const float* __restrict__ W2,
                        const float* __restrict__ W3) {
    int i = blockIdx.x * blockDim.x + threadIdx.x;   // float4 index
    const float* src; __half* dst; int off;
    if (i < 65536)       { src = W1; dst = g_W1h; off = i; }
    else if (i < 131072) { src = W2; dst = g_W2h; off = i - 65536; }
    else if (i < 163840) { src = W3; dst = g_W3h; off = i - 131072; }
    else return;
    float4 v = ((const float4*)src)[off];
    uint2 u;
    *(__half2*)&u.x = __floats2half2_rn(v.x, v.y);
    *(__half2*)&u.y = __floats2half2_rn(v.z, v.w);
    ((uint2*)dst)[off] = u;
}

// ---------------------------------------------------------------------------
// CSR construction
// ---------------------------------------------------------------------------

__global__ void k_zero_deg() {
    int i = blockIdx.x * blockDim.x + threadIdx.x;
    if (i < NN / 4) ((int4*)g_pos)[i] = make_int4(0, 0, 0, 0);
}

__global__ void k_hist(const int* __restrict__ dst) {
    int e = blockIdx.x * blockDim.x + threadIdx.x;
    if (e < EE) atomicAdd(&g_pos[dst[e]], 1);
}

// Shuffle-based scan: 1000 active threads x 20 counters (5 x int4 each).
__global__ void k_scan() {
    __shared__ int wsum[32];
    const int tid  = threadIdx.x;
    const int lane = tid & 31;
    const int wid  = tid >> 5;

    int4 v[5];
    int local = 0;
    const bool act = tid < 1000;
    if (act) {
        const int4* p = (const int4*)g_pos + tid * 5;
        #pragma unroll
        for (int i = 0; i < 5; i++) {
            v[i] = p[i];
            local += v[i].x + v[i].y + v[i].z + v[i].w;
        }
    }

    // warp inclusive scan (no barriers)
    int inc = local;
    #pragma unroll
    for (int o = 1; o < 32; o <<= 1) {
        int t = __shfl_up_sync(0xffffffffu, inc, o);
        if (lane >= o) inc += t;
    }
    if (lane == 31) wsum[wid] = inc;
    __syncthreads();

    if (wid == 0) {
        int w = wsum[lane];
        #pragma unroll
        for (int o = 1; o < 32; o <<= 1) {
            int t = __shfl_up_sync(0xffffffffu, w, o);
            if (lane >= o) w += t;
        }
        wsum[lane] = w;
    }
    __syncthreads();

    int run = (wid ? wsum[wid - 1] : 0) + (inc - local);  // exclusive prefix
    if (act) {
        int4* rp = (int4*)g_rowptr + tid * 5;
        int4* pp = (int4*)g_pos + tid * 5;
        #pragma unroll
        for (int i = 0; i < 5; i++) {
            int4 d = v[i];
            int4 r;
            r.x = run; run += d.x;
            r.y = run; run += d.y;
            r.z = run; run += d.z;
            r.w = run; run += d.w;
            rp[i] = r;
            pp[i] = r;
        }
    }
    if (tid == 0) g_rowptr[NN] = wsum[31];
}

__global__ void k_scatter(const int* __restrict__ src, const int* __restrict__ dst) {
    int e = blockIdx.x * blockDim.x + threadIdx.x;
    if (e < EE) {
        int idx = atomicAdd(&g_pos[dst[e]], 1);
        g_srcs[idx] = src[e];
    }
}

// ---------------------------------------------------------------------------
// fp16 tensor-core GEMM: C[M,N] = A[M,K] @ B[K,N]; C fp16, accum fp32.
// 128x128x32 tiles, 256 threads, 8 warps (2x4, warp tile 64x32), double buffer.
// ---------------------------------------------------------------------------

#define BM 128
#define BN 128
#define BK 32

__device__ __forceinline__ uint32_t smem_u32(const void* p) {
    return (uint32_t)__cvta_generic_to_shared(p);
}

__device__ __forceinline__ void ldm_x4(uint32_t* r, uint32_t addr) {
    asm volatile("ldmatrix.sync.aligned.m8n8.x4.shared.b16 {%0,%1,%2,%3}, [%4];"
                 : "=r"(r[0]), "=r"(r[1]), "=r"(r[2]), "=r"(r[3]) : "r"(addr));
}

__device__ __forceinline__ void ldm_x4_t(uint32_t* r, uint32_t addr) {
    asm volatile("ldmatrix.sync.aligned.m8n8.x4.trans.shared.b16 {%0,%1,%2,%3}, [%4];"
                 : "=r"(r[0]), "=r"(r[1]), "=r"(r[2]), "=r"(r[3]) : "r"(addr));
}

__device__ __forceinline__ void mma_f16(float* c, const uint32_t* a, const uint32_t* b) {
    asm volatile(
        "mma.sync.aligned.m16n8k16.row.col.f32.f16.f16.f32 "
        "{%0,%1,%2,%3}, {%4,%5,%6,%7}, {%8,%9}, {%0,%1,%2,%3};\n"
        : "+f"(c[0]), "+f"(c[1]), "+f"(c[2]), "+f"(c[3])
        : "r"(a[0]), "r"(a[1]), "r"(a[2]), "r"(a[3]), "r"(b[0]), "r"(b[1]));
}

template <int N, int K, bool AHALF>
__device__ __forceinline__ void gemm_f16_body(const void* __restrict__ Aptr,
                                              const __half* __restrict__ Bw,
                                              __half* __restrict__ C) {
    constexpr int M  = NN;
    constexpr int AS = BK + 8;    // 80B row stride
    constexpr int BS = BN + 8;    // 272B row stride
    __shared__ __half As[2][BM][AS];
    __shared__ __half Bs[2][BK][BS];

    const int tid  = threadIdx.x;
    const int bx   = blockIdx.x;
    const int by   = blockIdx.y;
    const int wid  = tid >> 5;
    const int lane = tid & 31;
    const int gid  = lane >> 2;
    const int tig  = lane & 3;

    const int wm0 = (wid & 1) * 64;
    const int wn0 = (wid >> 1) * 32;

    float acc[4][4][4];
    #pragma unroll
    for (int i = 0; i < 4; i++)
        #pragma unroll
        for (int j = 0; j < 4; j++)
            #pragma unroll
            for (int q = 0; q < 4; q++) acc[i][j][q] = 0.0f;

    uint4  aH[2];
    float4 aF[4];
    uint4  bH[2];

    auto loadGlobal = [&](int k0) {
        if (AHALF) {
            const __half* Ah = (const __half*)Aptr;
            #pragma unroll
            for (int l = 0; l < 2; l++) {
                int fidx = tid + l * 256;
                int row = fidx >> 2, col8 = fidx & 3;
                int grow = by * BM + row;
                aH[l] = (grow < M)
                    ? *(const uint4*)(Ah + (size_t)grow * K + k0 + col8 * 8)
                    : make_uint4(0u, 0u, 0u, 0u);
            }
        } else {
            const float* Af = (const float*)Aptr;
            #pragma unroll
            for (int l = 0; l < 4; l++) {
                int fidx = tid + l * 256;
                int row = fidx >> 3, col4 = fidx & 7;
                int grow = by * BM + row;
                aF[l] = (grow < M)
                    ? *(const float4*)(Af + (size_t)grow * K + k0 + col4 * 4)
                    : make_float4(0.f, 0.f, 0.f, 0.f);
            }
        }
        #pragma unroll
        for (int l = 0; l < 2; l++) {
            int fidx = tid + l * 256;
            int row = fidx >> 4, col8 = fidx & 15;
            bH[l] = *(const uint4*)(Bw + (size_t)(k0 + row) * N + bx * BN + col8 * 8);
        }
    };

    auto storeSmem = [&](int buf) {
        if (AHALF) {
            #pragma unroll
            for (int l = 0; l < 2; l++) {
                int fidx = tid + l * 256;
                int row = fidx >> 2, col8 = fidx & 3;
                *(uint4*)&As[buf][row][col8 * 8] = aH[l];
            }
        } else {
            #pragma unroll
            for (int l = 0; l < 4; l++) {
                int fidx = tid + l * 256;
                int row = fidx >> 3, col4 = fidx & 7;
                uint2 u;
                *(__half2*)&u.x = __floats2half2_rn(aF[l].x, aF[l].y);
                *(__half2*)&u.y = __floats2half2_rn(aF[l].z, aF[l].w);
                *(uint2*)&As[buf][row][col4 * 4] = u;
            }
        }
        #pragma unroll
        for (int l = 0; l < 2; l++) {
            int fidx = tid + l * 256;
            int row = fidx >> 4, col8 = fidx & 15;
            *(uint4*)&Bs[buf][row][col8 * 8] = bH[l];
        }
    };

    loadGlobal(0);
    storeSmem(0);
    __syncthreads();

    constexpr int NT = K / BK;
    int cur = 0;
    for (int kt = 0; kt < NT; kt++) {
        if (kt + 1 < NT) loadGlobal((kt + 1) * BK);

        #pragma unroll
        for (int ks = 0; ks < 2; ks++) {
            const int kb = ks * 16;
            uint32_t af[4][4], bf[4][2];
            #pragma unroll
            for (int mi = 0; mi < 4; mi++) {
                int row = wm0 + mi * 16 + (lane & 15);
                int col = kb + ((lane >> 4) << 3);
                ldm_x4(af[mi], smem_u32(&As[cur][row][col]));
            }
            #pragma unroll
            for (int nh = 0; nh < 2; nh++) {
                int row = kb + (lane & 15);
                int col = wn0 + nh * 16 + ((lane >> 4) << 3);
                uint32_t r[4];
                ldm_x4_t(r, smem_u32(&Bs[cur][row][col]));
                bf[nh * 2][0] = r[0]; bf[nh * 2][1] = r[1];
                bf[nh * 2 + 1][0] = r[2]; bf[nh * 2 + 1][1] = r[3];
            }
            #pragma unroll
            for (int mi = 0; mi < 4; mi++)
                #pragma unroll
                for (int ni = 0; ni < 4; ni++)
                    mma_f16(acc[mi][ni], af[mi], bf[ni]);
        }

        if (kt + 1 < NT) {
            storeSmem(cur ^ 1);
            __syncthreads();
            cur ^= 1;
        }
    }

    #pragma unroll
    for (int mi = 0; mi < 4; mi++) {
        #pragma unroll
        for (int ni = 0; ni < 4; ni++) {
            int row0 = by * BM + wm0 + mi * 16 + gid;
            int col  = bx * BN + wn0 + ni * 8 + tig * 2;
            if (row0 < M)
                *(__half2*)(C + (size_t)row0 * N + col) =
                    __floats2half2_rn(acc[mi][ni][0], acc[mi][ni][1]);
            int row1 = row0 + 8;
            if (row1 < M)
                *(__half2*)(C + (size_t)row1 * N + col) =
                    __floats2half2_rn(acc[mi][ni][2], acc[mi][ni][3]);
        }
    }
}

__global__ void __launch_bounds__(256) k_gemm_l1(const float* __restrict__ A) {
    gemm_f16_body<DHID, DIN, false>(A, g_W1h, g_Yh);
}
__global__ void __launch_bounds__(256) k_gemm_l2() {
    gemm_f16_body<DHID, DHID, true>(g_Hh, g_W2h, g_Yh);
}
__global__ void __launch_bounds__(256) k_gemm_l3() {
    gemm_f16_body<DOUT, DHID, true>(g_Hh, g_W3h, g_Y3h);
}

// ---------------------------------------------------------------------------
// Aggregation (fp16 gather, fp32 accumulate, fp16 output)
// ---------------------------------------------------------------------------

__device__ __forceinline__ void acc8(float* a, uint4 v) {
    float2 f;
    f = __half22float2(*(__half2*)&v.x); a[0] += f.x; a[1] += f.y;
    f = __half22float2(*(__half2*)&v.y); a[2] += f.x; a[3] += f.y;
    f = __half22float2(*(__half2*)&v.z); a[4] += f.x; a[5] += f.y;
    f = __half22float2(*(__half2*)&v.w); a[6] += f.x; a[7] += f.y;
}

__global__ void __launch_bounds__(128) k_agg_hid(const float* __restrict__ bias) {
    const int n    = blockIdx.x * 2 + (threadIdx.x >> 6);
    const int lane = threadIdx.x & 63;
    const int c    = lane * 8;
    const int beg  = g_rowptr[n];
    const int end  = g_rowptr[n + 1];

    float acc[8];
    #pragma unroll
    for (int q = 0; q < 8; q++) acc[q] = 0.0f;

    const uint4* Y = (const uint4*)(g_Yh);
    int i = beg;
    for (; i + 3 < end; i += 4) {
        int s0 = g_srcs[i], s1 = g_srcs[i + 1], s2 = g_srcs[i + 2], s3 = g_srcs[i + 3];
        uint4 v0 = Y[(size_t)s0 * 64 + lane];
        uint4 v1 = Y[(size_t)s1 * 64 + lane];
        uint4 v2 = Y[(size_t)s2 * 64 + lane];
        uint4 v3 = Y[(size_t)s3 * 64 + lane];
        acc8(acc, v0); acc8(acc, v1); acc8(acc, v2); acc8(acc, v3);
    }
    for (; i < end; i++) {
        uint4 v = Y[(size_t)g_srcs[i] * 64 + lane];
        acc8(acc, v);
    }

    uint4 o;
    __half2* oh = (__half2*)&o;
    #pragma unroll
    for (int q = 0; q < 4; q++) {
        float r0 = fmaxf(acc[2 * q]     + bias[c + 2 * q],     0.0f);
        float r1 = fmaxf(acc[2 * q + 1] + bias[c + 2 * q + 1], 0.0f);
        oh[q] = __floats2half2_rn(r0, r1);
    }
    *((uint4*)(g_Hh + (size_t)n * DHID + c)) = o;
}

__global__ void __launch_bounds__(128) k_agg_out(const float* __restrict__ bias) {
    const int n    = blockIdx.x * 4 + (threadIdx.x >> 5);
    const int lane = threadIdx.x & 31;
    const int c    = lane * 8;
    const int beg  = g_rowptr[n];
    const int end  = g_rowptr[n + 1];

    float acc[8];
    #pragma unroll
    for (int q = 0; q < 8; q++) acc[q] = 0.0f;

    const uint4* Y = (const uint4*)(g_Y3h);
    int i = beg;
    for (; i + 3 < end; i += 4) {
        int s0 = g_srcs[i], s1 = g_srcs[i + 1], s2 = g_srcs[i + 2], s3 = g_srcs[i + 3];
        uint4 v0 = Y[(size_t)s0 * 32 + lane];
        uint4 v1 = Y[(size_t)s1 * 32 + lane];
        uint4 v2 = Y[(size_t)s2 * 32 + lane];
        uint4 v3 = Y[(size_t)s3 * 32 + lane];
        acc8(acc, v0); acc8(acc, v1); acc8(acc, v2); acc8(acc, v3);
    }
    for (; i < end; i++) {
        uint4 v = Y[(size_t)g_srcs[i] * 32 + lane];
        acc8(acc, v);
    }

    uint4 o;
    __half2* oh = (__half2*)&o;
    #pragma unroll
    for (int q = 0; q < 4; q++)
        oh[q] = __floats2half2_rn(acc[2 * q] + bias[c + 2 * q],
                                  acc[2 * q + 1] + bias[c + 2 * q + 1]);
    *((uint4*)(g_Zh + (size_t)n * DOUT + c)) = o;
}

// ---------------------------------------------------------------------------
// Decode
// ---------------------------------------------------------------------------

__global__ void k_decode(const int* __restrict__ eli, float* __restrict__ out) {
    int g = blockIdx.x * blockDim.x + threadIdx.x;
    int w = g >> 5;
    int lane = g & 31;
    if (w >= LL) return;

    int a = eli[w];
    int b = eli[LL + w];
    uint4 va = ((const uint4*)(g_Zh + (size_t)a * DOUT))[lane];
    uint4 vb = ((const uint4*)(g_Zh + (size_t)b * DOUT))[lane];

    float s = 0.0f;
    const __half2* ha = (const __half2*)&va;
    const __half2* hb = (const __half2*)&vb;
    #pragma unroll
    for (int q = 0; q < 4; q++) {
        float2 fa = __half22float2(ha[q]);
        float2 fb = __half22float2(hb[q]);
        s += fa.x * fb.x + fa.y * fb.y;
    }

    #pragma unroll
    for (int o = 16; o; o >>= 1) s += __shfl_xor_sync(0xffffffffu, s, o);
    if (lane == 0) out[w] = s;
}

// ---------------------------------------------------------------------------
// Launch: CSR build on main stream, {W-cvt, GEMM-L1} on side stream, join.
// ---------------------------------------------------------------------------

extern "C" void kernel_launch(void* const* d_in, const int* in_sizes, int n_in,
                              void* d_out, int out_size) {
    (void)in_sizes; (void)n_in; (void)out_size;
    const float* x   = (const float*)d_in[0];
    const int*   ei  = (const int*)  d_in[1];
    const int*   eli = (const int*)  d_in[2];
    const float* W1  = (const float*)d_in[3];
    const float* b1  = (const float*)d_in[4];
    const float* W2  = (const float*)d_in[5];
    const float* b2  = (const float*)d_in[6];
    const float* W3  = (const float*)d_in[7];
    const float* b3  = (const float*)d_in[8];
    float* out = (float*)d_out;

    const int* src = ei;
    const int* dst = ei + EE;

    static cudaStream_t s2 = nullptr;
    static cudaEvent_t evFork = nullptr, evL1 = nullptr;
    if (!s2) {
        cudaStreamCreateWithFlags(&s2, cudaStreamNonBlocking);
        cudaEventCreateWithFlags(&evFork, cudaEventDisableTiming);
        cudaEventCreateWithFlags(&evL1, cudaEventDisableTiming);
    }

    const dim3 gHID(DHID / BN, (NN + BM - 1) / BM);
    const dim3 gOUT(DOUT / BN, (NN + BM - 1) / BM);

    // Fork: side stream does weight conversion + layer-1 GEMM
    cudaEventRecord(evFork, 0);
    cudaStreamWaitEvent(s2, evFork, 0);
    k_cvt_w<<<640, 256, 0, s2>>>(W1, W2, W3);
    k_gemm_l1<<<gHID, 256, 0, s2>>>(x);
    cudaEventRecord(evL1, s2);

    // Main stream: CSR build (independent of side-stream work)
    k_zero_deg<<<20, 256>>>();
    k_hist<<<(EE + 255) / 256, 256>>>(dst);
    k_scan<<<1, 1024>>>();
    k_scatter<<<(EE + 255) / 256, 256>>>(src, dst);

    // Join: aggregation needs both CSR and layer-1 GEMM output
    cudaStreamWaitEvent(0, evL1, 0);

    k_agg_hid<<<NN / 2, 128>>>(b1);
    k_gemm_l2<<<gHID, 256>>>();
    k_agg_hid<<<NN / 2, 128>>>(b2);
    k_gemm_l3<<<gOUT, 256>>>();
    k_agg_out<<<NN / 4, 128>>>(b3);
    k_decode<<<(LL * 32 + 255) / 256, 256>>>(eli, out);
}